// round 1
// baseline (speedup 1.0000x reference)
#include <cuda_runtime.h>
#include <math.h>

#define WS 11

// ---------------- static device state (no allocations allowed) --------------
__device__ float  g_gauss[WS];
__device__ double g_ssim_sum[5];
__device__ double g_cs_sum[5];
__device__ int    g_fmax[5];
__device__ int    g_fmin[5];

// scratch: pass1 output [5 fields][2 batch][S][S][Wo], sized for level 0
__device__ float g_s1[67092480];   // 10*192*192*182
// pass2 output [5][2][S][Ho][Wo]
__device__ float g_s2[63598080];   // 10*192*182*182
// pooled image pyramids (levels 1..4), both images
__device__ float g_p1[2021760];
__device__ float g_p2[2021760];

__constant__ long c_off[5] = {0, 0, 1769472, 1990656, 2018304};

// ---------------------------------------------------------------------------
__global__ void k_init() {
    int t = threadIdx.x;
    if (t == 0) {
        double v[WS], s = 0.0;
        for (int i = 0; i < WS; i++) {
            double d = (double)(i - 5);
            v[i] = exp(-d * d / 4.5);
            s += v[i];
        }
        for (int i = 0; i < WS; i++) g_gauss[i] = (float)(v[i] / s);
    }
    if (t < 5) {
        g_ssim_sum[t] = 0.0;
        g_cs_sum[t]   = 0.0;
        g_fmax[t]     = 0;
        g_fmin[t]     = 0;
    }
}

// ------------- range flags for L selection (img1 only) ----------------------
__global__ void k_flags(const float* __restrict__ img0, int lvl, long n) {
    const float* img = (lvl == 0) ? img0 : (g_p1 + c_off[lvl]);
    bool mx = false, mn = false;
    for (long i = blockIdx.x * (long)blockDim.x + threadIdx.x; i < n;
         i += (long)gridDim.x * blockDim.x) {
        float v = img[i];
        mx |= (v > 128.0f);
        mn |= (v < -0.5f);
    }
    unsigned bm = __ballot_sync(0xffffffffu, mx);
    unsigned bn = __ballot_sync(0xffffffffu, mn);
    if ((threadIdx.x & 31) == 0) {
        if (bm) atomicOr(&g_fmax[lvl], 1);
        if (bn) atomicOr(&g_fmin[lvl], 1);
    }
}

// ------------- pass 1: 11-tap conv along W, emit 5 fields -------------------
// block = one (b,d,h) row of length S; blockDim = S; smem = 2*S floats
__global__ void k_pass1(const float* __restrict__ i1_0,
                        const float* __restrict__ i2_0, int lvl, int S) {
    extern __shared__ float sm[];
    float* s1 = sm;
    float* s2 = sm + S;
    const float* i1 = (lvl == 0) ? i1_0 : (g_p1 + c_off[lvl]);
    const float* i2 = (lvl == 0) ? i2_0 : (g_p2 + c_off[lvl]);
    long row = blockIdx.x;             // b*S*S + d*S + h
    int  t   = threadIdx.x;
    s1[t] = i1[row * S + t];
    s2[t] = i2[row * S + t];
    __syncthreads();
    int Wo = S - 10;
    if (t < Wo) {
        float w[WS];
#pragma unroll
        for (int k = 0; k < WS; k++) w[k] = g_gauss[k];
        float a1 = 0.f, a2 = 0.f, a11 = 0.f, a22 = 0.f, a12 = 0.f;
#pragma unroll
        for (int k = 0; k < WS; k++) {
            float x = s1[t + k], y = s2[t + k];
            a1  = fmaf(w[k], x, a1);
            a2  = fmaf(w[k], y, a2);
            a11 = fmaf(w[k] * x, x, a11);
            a22 = fmaf(w[k] * y, y, a22);
            a12 = fmaf(w[k] * x, y, a12);
        }
        long fsz = 2L * S * S * Wo;
        long o   = row * Wo + t;
        g_s1[o]           = a1;
        g_s1[fsz + o]     = a2;
        g_s1[2 * fsz + o] = a11;
        g_s1[3 * fsz + o] = a22;
        g_s1[4 * fsz + o] = a12;
    }
}

// ------------- pass 2: 11-tap conv along H over 10 channels -----------------
__global__ void k_pass2(int S) {
    int  Wo    = S - 10, Ho = S - 10;
    long total = 10L * S * Ho * Wo;
    float w[WS];
#pragma unroll
    for (int k = 0; k < WS; k++) w[k] = g_gauss[k];
    for (long idx = blockIdx.x * (long)blockDim.x + threadIdx.x; idx < total;
         idx += (long)gridDim.x * blockDim.x) {
        int  wo = (int)(idx % Wo);
        long r  = idx / Wo;
        int  ho = (int)(r % Ho);
        long q  = r / Ho;              // (f*2 + b)*S + d   in [0, 10*S)
        const float* in = g_s1 + q * (long)S * Wo + wo;
        float acc = 0.f;
#pragma unroll
        for (int k = 0; k < WS; k++) acc = fmaf(w[k], in[(long)(ho + k) * Wo], acc);
        g_s2[q * (long)Ho * Wo + (long)ho * Wo + wo] = acc;
    }
}

// ------------- pass 3: D conv + SSIM/CS map + mean reduction ----------------
__device__ __forceinline__ float warp_sum(float v) {
#pragma unroll
    for (int o = 16; o; o >>= 1) v += __shfl_down_sync(0xffffffffu, v, o);
    return v;
}

__global__ void k_pass3(int S, int lvl) {
    int  Wo = S - 10, Ho = Wo, Do = Wo;
    long nmap = 2L * Do * Ho * Wo;
    long HW   = (long)Ho * Wo;
    long fstr = 2L * S * HW;           // per-field stride in g_s2
    float w[WS];
#pragma unroll
    for (int k = 0; k < WS; k++) w[k] = g_gauss[k];

    float maxv = g_fmax[lvl] ? 255.0f : 1.0f;
    float minv = g_fmin[lvl] ? -1.0f : 0.0f;
    float L    = maxv - minv;
    float C1   = (0.01f * L) * (0.01f * L);
    float C2   = (0.03f * L) * (0.03f * L);

    float sum_s = 0.f, sum_c = 0.f;
    for (long idx = blockIdx.x * (long)blockDim.x + threadIdx.x; idx < nmap;
         idx += (long)gridDim.x * blockDim.x) {
        int  wo = (int)(idx % Wo);
        long r  = idx / Wo;
        int  ho = (int)(r % Ho);
        r /= Ho;
        int dd = (int)(r % Do);
        int b  = (int)(r / Do);
        long o = (long)ho * Wo + wo;
        float a0 = 0.f, a1 = 0.f, a2 = 0.f, a3 = 0.f, a4 = 0.f;
#pragma unroll
        for (int k = 0; k < WS; k++) {
            long base = ((long)(b * S + dd + k)) * HW + o;
            float wk  = w[k];
            a0 = fmaf(wk, g_s2[base],            a0);
            a1 = fmaf(wk, g_s2[fstr + base],     a1);
            a2 = fmaf(wk, g_s2[2 * fstr + base], a2);
            a3 = fmaf(wk, g_s2[3 * fstr + base], a3);
            a4 = fmaf(wk, g_s2[4 * fstr + base], a4);
        }
        float mu1 = a0, mu2 = a1;
        float s1q = a2 - mu1 * mu1;
        float s2q = a3 - mu2 * mu2;
        float s12 = a4 - mu1 * mu2;
        float v1  = 2.0f * s12 + C2;
        float v2  = s1q + s2q + C2;
        float cs  = v1 / v2;
        float smv = (2.0f * mu1 * mu2 + C1) * v1 /
                    ((mu1 * mu1 + mu2 * mu2 + C1) * v2);
        sum_c += cs;
        sum_s += smv;
    }
    sum_c = warp_sum(sum_c);
    sum_s = warp_sum(sum_s);
    __shared__ float shc[8], shs[8];
    int lane = threadIdx.x & 31, wid = threadIdx.x >> 5;
    if (lane == 0) { shc[wid] = sum_c; shs[wid] = sum_s; }
    __syncthreads();
    if (threadIdx.x == 0) {
        float tc = 0.f, ts = 0.f;
        int nw = blockDim.x >> 5;
        for (int i = 0; i < nw; i++) { tc += shc[i]; ts += shs[i]; }
        atomicAdd(&g_cs_sum[lvl],   (double)tc);
        atomicAdd(&g_ssim_sum[lvl], (double)ts);
    }
}

// ------------- avg pool 2x2x2 (both images) ---------------------------------
__global__ void k_pool(const float* __restrict__ i1_0,
                       const float* __restrict__ i2_0, int lvl, int S) {
    const float* i1 = (lvl == 0) ? i1_0 : (g_p1 + c_off[lvl]);
    const float* i2 = (lvl == 0) ? i2_0 : (g_p2 + c_off[lvl]);
    float* o1 = g_p1 + c_off[lvl + 1];
    float* o2 = g_p2 + c_off[lvl + 1];
    int  T = S / 2;
    long n = 2L * T * T * T;
    for (long idx = blockIdx.x * (long)blockDim.x + threadIdx.x; idx < n;
         idx += (long)gridDim.x * blockDim.x) {
        int x = (int)(idx % T);
        long r = idx / T;
        int y = (int)(r % T); r /= T;
        int z = (int)(r % T);
        int b = (int)(r / T);
        long base = (((long)b * S + 2 * z) * S + 2 * y) * S + 2 * x;
        float s1 = 0.f, s2 = 0.f;
#pragma unroll
        for (int dz = 0; dz < 2; dz++)
#pragma unroll
            for (int dy = 0; dy < 2; dy++)
#pragma unroll
                for (int dx = 0; dx < 2; dx++) {
                    long p = base + (long)dz * S * S + (long)dy * S + dx;
                    s1 += i1[p];
                    s2 += i2[p];
                }
        o1[idx] = s1 * 0.125f;
        o2[idx] = s2 * 0.125f;
    }
}

// ------------- final combine -------------------------------------------------
__global__ void k_final(float* out) {
    const double W[5]   = {0.0448, 0.2856, 0.3001, 0.2363, 0.1333};
    const double cnt[5] = {12057136.0, 1272112.0, 109744.0, 5488.0, 16.0};
    double p = 1.0;
    for (int l = 0; l < 4; l++) p *= pow(g_cs_sum[l] / cnt[l], W[l]);
    p *= pow(g_ssim_sum[4] / cnt[4], W[4]);
    out[0] = (float)p;
}

// ---------------------------------------------------------------------------
extern "C" void kernel_launch(void* const* d_in, const int* in_sizes, int n_in,
                              void* d_out, int out_size) {
    const float* img1 = (const float*)d_in[0];
    const float* img2 = (const float*)d_in[1];

    k_init<<<1, 32>>>();

    int S = 192;
    for (int lvl = 0; lvl < 5; lvl++) {
        long n = 2L * S * S * S;
        long fb = (n + 255) / 256;
        if (fb > 4096) fb = 4096;
        k_flags<<<(int)fb, 256>>>(img1, lvl, n);

        k_pass1<<<2 * S * S, S, 2 * S * (int)sizeof(float)>>>(img1, img2, lvl, S);

        int  Wo = S - 10;
        long t2 = 10L * S * Wo * Wo;
        k_pass2<<<(int)((t2 + 255) / 256), 256>>>(S);

        long nmap = 2L * Wo * Wo * Wo;
        k_pass3<<<(int)((nmap + 255) / 256), 256>>>(S, lvl);

        if (lvl < 4) {
            long np = 2L * (S / 2) * (S / 2) * (S / 2);
            k_pool<<<(int)((np + 255) / 256), 256>>>(img1, img2, lvl, S);
        }
        S /= 2;
    }
    k_final<<<1, 1>>>((float*)d_out);
}

// round 2
// speedup vs baseline: 2.1150x; 2.1150x over previous
#include <cuda_runtime.h>
#include <math.h>

#define WS 11
#define TH 8   // pass2 outputs per thread (along H)
#define TD 4   // pass3 outputs per thread (along D)

// ---------------- static device state (no allocations allowed) --------------
__device__ float  g_gauss[WS];
__device__ double g_ssim_sum[5];
__device__ double g_cs_sum[5];
__device__ int    g_fmax[5];
__device__ int    g_fmin[5];

// pass1 output [5 fields][2 batch][S][S][Wo], sized for level 0
__device__ float g_s1[67092480];   // 10*192*192*182
// pass2 output [5][2][S][Ho][Wo]
__device__ float g_s2[63598080];   // 10*192*182*182
// pooled image pyramids (levels 1..4), both images
__device__ float g_p1[2021760];
__device__ float g_p2[2021760];

__constant__ long c_off[5] = {0, 0, 1769472, 1990656, 2018304};

// ---------------------------------------------------------------------------
__global__ void k_init() {
    int t = threadIdx.x;
    if (t == 0) {
        double v[WS], s = 0.0;
        for (int i = 0; i < WS; i++) {
            double d = (double)(i - 5);
            v[i] = exp(-d * d / 4.5);
            s += v[i];
        }
        for (int i = 0; i < WS; i++) g_gauss[i] = (float)(v[i] / s);
    }
    if (t < 5) {
        g_ssim_sum[t] = 0.0;
        g_cs_sum[t]   = 0.0;
        g_fmax[t]     = 0;
        g_fmin[t]     = 0;
    }
}

// ------------- range flags for L selection (img1 only) ----------------------
__global__ void k_flags(const float* __restrict__ img0, int lvl, long n) {
    const float* img = (lvl == 0) ? img0 : (g_p1 + c_off[lvl]);
    bool mx = false, mn = false;
    for (long i = blockIdx.x * (long)blockDim.x + threadIdx.x; i < n;
         i += (long)gridDim.x * blockDim.x) {
        float v = img[i];
        mx |= (v > 128.0f);
        mn |= (v < -0.5f);
    }
    unsigned bm = __ballot_sync(0xffffffffu, mx);
    unsigned bn = __ballot_sync(0xffffffffu, mn);
    if ((threadIdx.x & 31) == 0) {
        if (bm) atomicOr(&g_fmax[lvl], 1);
        if (bn) atomicOr(&g_fmin[lvl], 1);
    }
}

// ------------- pass 1: 11-tap conv along W, emit 5 fields -------------------
// block = one (b,d,h) row of length S; blockDim = S; smem = 2*S floats
__global__ void k_pass1(const float* __restrict__ i1_0,
                        const float* __restrict__ i2_0, int lvl, int S) {
    extern __shared__ float sm[];
    float* s1 = sm;
    float* s2 = sm + S;
    const float* i1 = (lvl == 0) ? i1_0 : (g_p1 + c_off[lvl]);
    const float* i2 = (lvl == 0) ? i2_0 : (g_p2 + c_off[lvl]);
    long row = blockIdx.x;             // b*S*S + d*S + h
    int  t   = threadIdx.x;
    s1[t] = i1[row * S + t];
    s2[t] = i2[row * S + t];
    __syncthreads();
    int Wo = S - 10;
    if (t < Wo) {
        float w[WS];
#pragma unroll
        for (int k = 0; k < WS; k++) w[k] = g_gauss[k];
        float a1 = 0.f, a2 = 0.f, a11 = 0.f, a22 = 0.f, a12 = 0.f;
#pragma unroll
        for (int k = 0; k < WS; k++) {
            float x = s1[t + k], y = s2[t + k];
            a1  = fmaf(w[k], x, a1);
            a2  = fmaf(w[k], y, a2);
            a11 = fmaf(w[k] * x, x, a11);
            a22 = fmaf(w[k] * y, y, a22);
            a12 = fmaf(w[k] * x, y, a12);
        }
        long fsz = 2L * S * S * Wo;
        long o   = row * Wo + t;
        g_s1[o]           = a1;
        g_s1[fsz + o]     = a2;
        g_s1[2 * fsz + o] = a11;
        g_s1[3 * fsz + o] = a22;
        g_s1[4 * fsz + o] = a12;
    }
}

// ------------- pass 2: 11-tap conv along H, TH outputs per thread -----------
// grid: x = wo tiles (blockDim threads), y = ho tiles of TH, z = q in [0,10*S)
__global__ void k_pass2(int S) {
    int Wo = S - 10, Ho = S - 10;
    int wo = blockIdx.x * blockDim.x + threadIdx.x;
    if (wo >= Wo) return;
    int ho0 = blockIdx.y * TH;
    int q   = blockIdx.z;
    const float* in  = g_s1 + (long)q * S  * Wo + wo;
    float*       out = g_s2 + (long)q * Ho * Wo + wo;
    float w[WS];
#pragma unroll
    for (int k = 0; k < WS; k++) w[k] = g_gauss[k];
    float acc[TH];
#pragma unroll
    for (int j = 0; j < TH; j++) acc[j] = 0.f;
#pragma unroll
    for (int k = 0; k < TH + 10; k++) {
        int h = ho0 + k;
        float v = (h < S) ? in[(long)h * Wo] : 0.f;
#pragma unroll
        for (int j = 0; j < TH; j++) {
            int t = k - j;
            if (t >= 0 && t < WS) acc[j] = fmaf(w[t], v, acc[j]);
        }
    }
#pragma unroll
    for (int j = 0; j < TH; j++) {
        int ho = ho0 + j;
        if (ho < Ho) out[(long)ho * Wo] = acc[j];
    }
}

// ------------- pass 3: D conv + SSIM/CS + mean, TD outputs per thread -------
__device__ __forceinline__ float warp_sum(float v) {
#pragma unroll
    for (int o = 16; o; o >>= 1) v += __shfl_down_sync(0xffffffffu, v, o);
    return v;
}

// grid: x = wo tiles, y = ho in [0,Ho), z = b*ntiles + dtile
__global__ void k_pass3(int S, int lvl, int ntiles) {
    int  Wo = S - 10, Ho = Wo, Do = Wo;
    long HW   = (long)Ho * Wo;
    long fstr = 2L * S * HW;
    int  wo = blockIdx.x * blockDim.x + threadIdx.x;
    int  ho = blockIdx.y;
    int  b  = blockIdx.z / ntiles;
    int  d0 = (blockIdx.z % ntiles) * TD;
    bool act = (wo < Wo);

    float w[WS];
#pragma unroll
    for (int k = 0; k < WS; k++) w[k] = g_gauss[k];

    float A0[TD], A1[TD], A2[TD], A3[TD], A4[TD];
#pragma unroll
    for (int j = 0; j < TD; j++) { A0[j]=A1[j]=A2[j]=A3[j]=A4[j]=0.f; }

    if (act) {
        const float* base0 = g_s2 + (long)ho * Wo + wo;
#pragma unroll
        for (int k = 0; k < TD + 10; k++) {
            int d = d0 + k;
            if (d < S) {
                long off = ((long)(b * S + d)) * HW;
                float v0 = base0[off];
                float v1 = base0[fstr + off];
                float v2 = base0[2 * fstr + off];
                float v3 = base0[3 * fstr + off];
                float v4 = base0[4 * fstr + off];
#pragma unroll
                for (int j = 0; j < TD; j++) {
                    int t = k - j;
                    if (t >= 0 && t < WS) {
                        float wk = w[t];
                        A0[j] = fmaf(wk, v0, A0[j]);
                        A1[j] = fmaf(wk, v1, A1[j]);
                        A2[j] = fmaf(wk, v2, A2[j]);
                        A3[j] = fmaf(wk, v3, A3[j]);
                        A4[j] = fmaf(wk, v4, A4[j]);
                    }
                }
            }
        }
    }

    float maxv = g_fmax[lvl] ? 255.0f : 1.0f;
    float minv = g_fmin[lvl] ? -1.0f : 0.0f;
    float L    = maxv - minv;
    float C1   = (0.01f * L) * (0.01f * L);
    float C2   = (0.03f * L) * (0.03f * L);

    float sum_s = 0.f, sum_c = 0.f;
    if (act) {
#pragma unroll
        for (int j = 0; j < TD; j++) {
            if (d0 + j < Do) {
                float mu1 = A0[j], mu2 = A1[j];
                float s1q = A2[j] - mu1 * mu1;
                float s2q = A3[j] - mu2 * mu2;
                float s12 = A4[j] - mu1 * mu2;
                float v1  = 2.0f * s12 + C2;
                float v2  = s1q + s2q + C2;
                sum_c += v1 / v2;
                sum_s += (2.0f * mu1 * mu2 + C1) * v1 /
                         ((mu1 * mu1 + mu2 * mu2 + C1) * v2);
            }
        }
    }
    sum_c = warp_sum(sum_c);
    sum_s = warp_sum(sum_s);
    __shared__ float shc[8], shs[8];
    int lane = threadIdx.x & 31, wid = threadIdx.x >> 5;
    if (lane == 0) { shc[wid] = sum_c; shs[wid] = sum_s; }
    __syncthreads();
    if (threadIdx.x == 0) {
        float tc = 0.f, ts = 0.f;
        int nw = blockDim.x >> 5;
        for (int i = 0; i < nw; i++) { tc += shc[i]; ts += shs[i]; }
        atomicAdd(&g_cs_sum[lvl],   (double)tc);
        atomicAdd(&g_ssim_sum[lvl], (double)ts);
    }
}

// ------------- avg pool 2x2x2 (both images) ---------------------------------
__global__ void k_pool(const float* __restrict__ i1_0,
                       const float* __restrict__ i2_0, int lvl, int S) {
    const float* i1 = (lvl == 0) ? i1_0 : (g_p1 + c_off[lvl]);
    const float* i2 = (lvl == 0) ? i2_0 : (g_p2 + c_off[lvl]);
    float* o1 = g_p1 + c_off[lvl + 1];
    float* o2 = g_p2 + c_off[lvl + 1];
    int  T = S / 2;
    long n = 2L * T * T * T;
    for (long idx = blockIdx.x * (long)blockDim.x + threadIdx.x; idx < n;
         idx += (long)gridDim.x * blockDim.x) {
        int x = (int)(idx % T);
        long r = idx / T;
        int y = (int)(r % T); r /= T;
        int z = (int)(r % T);
        int b = (int)(r / T);
        long base = (((long)b * S + 2 * z) * S + 2 * y) * S + 2 * x;
        float s1 = 0.f, s2 = 0.f;
#pragma unroll
        for (int dz = 0; dz < 2; dz++)
#pragma unroll
            for (int dy = 0; dy < 2; dy++)
#pragma unroll
                for (int dx = 0; dx < 2; dx++) {
                    long p = base + (long)dz * S * S + (long)dy * S + dx;
                    s1 += i1[p];
                    s2 += i2[p];
                }
        o1[idx] = s1 * 0.125f;
        o2[idx] = s2 * 0.125f;
    }
}

// ------------- final combine -------------------------------------------------
__global__ void k_final(float* out) {
    const double W[5]   = {0.0448, 0.2856, 0.3001, 0.2363, 0.1333};
    const double cnt[5] = {12057136.0, 1272112.0, 109744.0, 5488.0, 16.0};
    double p = 1.0;
    for (int l = 0; l < 4; l++) p *= pow(g_cs_sum[l] / cnt[l], W[l]);
    p *= pow(g_ssim_sum[4] / cnt[4], W[4]);
    out[0] = (float)p;
}

// ---------------------------------------------------------------------------
extern "C" void kernel_launch(void* const* d_in, const int* in_sizes, int n_in,
                              void* d_out, int out_size) {
    const float* img1 = (const float*)d_in[0];
    const float* img2 = (const float*)d_in[1];

    k_init<<<1, 32>>>();

    int S = 192;
    for (int lvl = 0; lvl < 5; lvl++) {
        long n = 2L * S * S * S;
        long fb = (n + 255) / 256;
        if (fb > 4096) fb = 4096;
        k_flags<<<(int)fb, 256>>>(img1, lvl, n);

        k_pass1<<<2 * S * S, S, 2 * S * (int)sizeof(float)>>>(img1, img2, lvl, S);

        int Wo = S - 10, Ho = S - 10;
        {
            dim3 grid((Wo + 127) / 128, (Ho + TH - 1) / TH, 10 * S);
            k_pass2<<<grid, 128>>>(S);
        }
        {
            int ntiles = (Wo + TD - 1) / TD;
            dim3 grid((Wo + 127) / 128, Ho, 2 * ntiles);
            k_pass3<<<grid, 128>>>(S, lvl, ntiles);
        }

        if (lvl < 4) {
            long np = 2L * (S / 2) * (S / 2) * (S / 2);
            k_pool<<<(int)((np + 255) / 256), 256>>>(img1, img2, lvl, S);
        }
        S /= 2;
    }
    k_final<<<1, 1>>>((float*)d_out);
}

// round 5
// speedup vs baseline: 3.4209x; 1.6175x over previous
#include <cuda_runtime.h>
#include <math.h>

#define WSZ 11

// Gaussian weights (sigma=1.5, ws=11) as compile-time constants -> FFMA-imm
__device__ constexpr float CWA[WSZ] = {
    0.00102838f, 0.00759875f, 0.03600080f, 0.10936069f, 0.21300554f,
    0.26601173f, 0.21300554f, 0.10936069f, 0.03600080f, 0.00759875f,
    0.00102838f};

// ---------------- static device state (no allocations allowed) --------------
__device__ double g_ssim_sum[5];
__device__ double g_cs_sum[5];
__device__ int    g_fmax[5];
__device__ int    g_fmin[5];

// pass1 out: [5 fields][2][S][S][WP]  (level0: 10*192*192*184)
__device__ float g_s1[67829760];
// pass2 out: [5 fields][2][S][Ho][WP] (level0: 10*192*182*184)
__device__ float g_s2[64289280];
// pooled pyramids (levels 1..4)
__device__ float g_p1[2021760];
__device__ float g_p2[2021760];

static const long h_off[5] = {0, 0, 1769472, 1990656, 2018304};

// ---------------------------------------------------------------------------
__global__ void k_init() {
    int t = threadIdx.x;
    if (t < 5) {
        g_ssim_sum[t] = 0.0;
        g_cs_sum[t]   = 0.0;
        g_fmax[t]     = 0;
        g_fmin[t]     = 0;
    }
}

// ------------- pass 1: W-conv, 5 fields, 4 outputs/thread, flags fused ------
template <int S>
__global__ void k_pass1(const float* __restrict__ i1_0,
                        const float* __restrict__ i2_0, int lvl, long poff) {
    constexpr int  Wo  = S - 10;
    constexpr int  WP  = (Wo + 3) & ~3;
    constexpr int  WP4 = WP / 4;
    constexpr int  RPB = (192 / WP4) < 1 ? 1 : (192 / WP4);
    constexpr int  SP  = S + 8;                 // padded row, mult of 4
    constexpr long FSZ = 2L * S * S * WP;

    __shared__ float s1[RPB * SP];
    __shared__ float s2[RPB * SP];
    __shared__ int   sfl;

    const float* i1 = (lvl == 0) ? i1_0 : (g_p1 + poff);
    const float* i2 = (lvl == 0) ? i2_0 : (g_p2 + poff);

    const int tid  = threadIdx.x;
    const int rows = 2 * S * S;
    const int row0 = blockIdx.x * RPB;
    if (tid == 0) sfl = 0;

    bool mx = false, mn = false;
    for (int idx = tid; idx < RPB * SP; idx += WP4 * RPB) {
        int rr = idx / SP, ii = idx % SP;
        int grow = row0 + rr;
        float v1 = 0.f, v2 = 0.f;
        if (grow < rows && ii < S) {
            long gb = (long)grow * S + ii;
            v1 = i1[gb];
            v2 = i2[gb];
        }
        s1[idx] = v1;
        s2[idx] = v2;
        mx |= (v1 > 128.0f);
        mn |= (v1 < -0.5f);
    }
    __syncthreads();
    if (mx | mn) atomicOr(&sfl, (mx ? 1 : 0) | (mn ? 2 : 0));

    const int r = tid / WP4, t = tid - r * WP4;
    const int grow = row0 + r;
    if (grow < rows) {
        float xs[16], ys[16];
        {
            const float4* p1 = (const float4*)&s1[r * SP + 4 * t];
            const float4* p2 = (const float4*)&s2[r * SP + 4 * t];
#pragma unroll
            for (int m = 0; m < 4; m++) {
                float4 a = p1[m], b = p2[m];
                xs[4 * m] = a.x; xs[4 * m + 1] = a.y; xs[4 * m + 2] = a.z; xs[4 * m + 3] = a.w;
                ys[4 * m] = b.x; ys[4 * m + 1] = b.y; ys[4 * m + 2] = b.z; ys[4 * m + 3] = b.w;
            }
        }
        float xx[14], yy[14], xy[14];
#pragma unroll
        for (int m = 0; m < 14; m++) {
            xx[m] = xs[m] * xs[m];
            yy[m] = ys[m] * ys[m];
            xy[m] = xs[m] * ys[m];
        }
        float a1[4] = {0, 0, 0, 0}, a2[4] = {0, 0, 0, 0}, b1[4] = {0, 0, 0, 0},
              b2[4] = {0, 0, 0, 0}, b3[4] = {0, 0, 0, 0};
#pragma unroll
        for (int k = 0; k < WSZ; k++) {
            const float w = CWA[k];
#pragma unroll
            for (int j = 0; j < 4; j++) {
                a1[j] = fmaf(w, xs[k + j], a1[j]);
                a2[j] = fmaf(w, ys[k + j], a2[j]);
                b1[j] = fmaf(w, xx[k + j], b1[j]);
                b2[j] = fmaf(w, yy[k + j], b2[j]);
                b3[j] = fmaf(w, xy[k + j], b3[j]);
            }
        }
        long o = (long)grow * WP + 4 * t;
        float4 v;
        v.x = a1[0]; v.y = a1[1]; v.z = a1[2]; v.w = a1[3];
        *(float4*)&g_s1[o] = v;
        v.x = a2[0]; v.y = a2[1]; v.z = a2[2]; v.w = a2[3];
        *(float4*)&g_s1[FSZ + o] = v;
        v.x = b1[0]; v.y = b1[1]; v.z = b1[2]; v.w = b1[3];
        *(float4*)&g_s1[2 * FSZ + o] = v;
        v.x = b2[0]; v.y = b2[1]; v.z = b2[2]; v.w = b2[3];
        *(float4*)&g_s1[3 * FSZ + o] = v;
        v.x = b3[0]; v.y = b3[1]; v.z = b3[2]; v.w = b3[3];
        *(float4*)&g_s1[4 * FSZ + o] = v;
    }
    __syncthreads();
    if (tid == 0 && sfl) {
        if ((sfl & 1) && !g_fmax[lvl]) atomicOr(&g_fmax[lvl], 1);
        if ((sfl & 2) && !g_fmin[lvl]) atomicOr(&g_fmin[lvl], 1);
    }
}

// ------------- pass 2: H-conv, float4 x TH outputs per thread ---------------
template <int S>
__global__ void k_pass2() {
    constexpr int Wo = S - 10, Ho = S - 10;
    constexpr int WP  = (Wo + 3) & ~3;
    constexpr int NQ  = WP / 4;
    constexpr int TH  = 12;
    constexpr int NHT = (Ho + TH - 1) / TH;
    constexpr int TOT = 10 * S * NHT * NQ;

    int idx = blockIdx.x * blockDim.x + threadIdx.x;
    if (idx >= TOT) return;
    int quad = idx % NQ;
    int t    = idx / NQ;
    int ht   = t % NHT;
    int q    = t / NHT;
    int ho0  = ht * TH;

    const float* in = g_s1 + (long)q * S * WP + quad * 4;
    float4 acc[TH];
#pragma unroll
    for (int j = 0; j < TH; j++) acc[j] = make_float4(0.f, 0.f, 0.f, 0.f);

#pragma unroll
    for (int k = 0; k < TH + 10; k++) {
        int h = ho0 + k;
        if (h < S) {
            float4 v = *(const float4*)(in + h * WP);
#pragma unroll
            for (int j = 0; j < TH; j++) {
                int tt = k - j;
                if (tt >= 0 && tt < WSZ) {
                    const float w = CWA[tt];
                    acc[j].x = fmaf(w, v.x, acc[j].x);
                    acc[j].y = fmaf(w, v.y, acc[j].y);
                    acc[j].z = fmaf(w, v.z, acc[j].z);
                    acc[j].w = fmaf(w, v.w, acc[j].w);
                }
            }
        }
    }
    float* out = g_s2 + (long)q * Ho * WP + quad * 4;
#pragma unroll
    for (int j = 0; j < TH; j++) {
        int ho = ho0 + j;
        if (ho < Ho) *(float4*)(out + ho * WP) = acc[j];
    }
}

// ------------- pass 3: D-conv + SSIM/CS + reduction, float2 x TD ------------
__device__ __forceinline__ float warp_sum(float v) {
#pragma unroll
    for (int o = 16; o; o >>= 1) v += __shfl_down_sync(0xffffffffu, v, o);
    return v;
}

template <int S>
__global__ void k_pass3(int lvl) {
    constexpr int  Wo  = S - 10, Ho = Wo, Do = Wo;
    constexpr int  WP  = (Wo + 3) & ~3;
    constexpr int  NQ2 = WP / 2;
    constexpr int  TD  = 6;
    constexpr int  NDT = (Do + TD - 1) / TD;
    constexpr long HWP = (long)Ho * WP;
    constexpr long FST = 2L * S * HWP;
    constexpr int  TOT = 2 * NDT * Ho * NQ2;

    int idx = blockIdx.x * blockDim.x + threadIdx.x;
    float sum_s = 0.f, sum_c = 0.f;
    if (idx < TOT) {
        int p  = idx % NQ2;
        int t  = idx / NQ2;
        int ho = t % Ho;
        int t2 = t / Ho;
        int dt = t2 % NDT;
        int b  = t2 / NDT;
        int d0 = dt * TD;

        const float* base = g_s2 + (long)b * S * HWP + (long)ho * WP + 2 * p;
        float2 A0[TD], A1[TD], A2[TD], A3[TD], A4[TD];
#pragma unroll
        for (int j = 0; j < TD; j++) {
            A0[j] = A1[j] = A2[j] = A3[j] = A4[j] = make_float2(0.f, 0.f);
        }
#pragma unroll
        for (int k = 0; k < TD + 10; k++) {
            int d = d0 + k;
            if (d < S) {
                const float* pp = base + (long)d * HWP;
                float2 v0 = *(const float2*)(pp);
                float2 v1 = *(const float2*)(pp + FST);
                float2 v2 = *(const float2*)(pp + 2 * FST);
                float2 v3 = *(const float2*)(pp + 3 * FST);
                float2 v4 = *(const float2*)(pp + 4 * FST);
#pragma unroll
                for (int j = 0; j < TD; j++) {
                    int tt = k - j;
                    if (tt >= 0 && tt < WSZ) {
                        const float w = CWA[tt];
                        A0[j].x = fmaf(w, v0.x, A0[j].x); A0[j].y = fmaf(w, v0.y, A0[j].y);
                        A1[j].x = fmaf(w, v1.x, A1[j].x); A1[j].y = fmaf(w, v1.y, A1[j].y);
                        A2[j].x = fmaf(w, v2.x, A2[j].x); A2[j].y = fmaf(w, v2.y, A2[j].y);
                        A3[j].x = fmaf(w, v3.x, A3[j].x); A3[j].y = fmaf(w, v3.y, A3[j].y);
                        A4[j].x = fmaf(w, v4.x, A4[j].x); A4[j].y = fmaf(w, v4.y, A4[j].y);
                    }
                }
            }
        }
        float maxv = g_fmax[lvl] ? 255.0f : 1.0f;
        float minv = g_fmin[lvl] ? -1.0f : 0.0f;
        float L  = maxv - minv;
        float C1 = (0.01f * L) * (0.01f * L);
        float C2 = (0.03f * L) * (0.03f * L);
        bool lane0 = (2 * p) < Wo;
        bool lane1 = (2 * p + 1) < Wo;
#pragma unroll
        for (int j = 0; j < TD; j++) {
            if (d0 + j < Do) {
                if (lane0) {
                    float mu1 = A0[j].x, mu2 = A1[j].x;
                    float v1 = 2.0f * (A4[j].x - mu1 * mu2) + C2;
                    float v2 = (A2[j].x - mu1 * mu1) + (A3[j].x - mu2 * mu2) + C2;
                    sum_c += v1 / v2;
                    sum_s += (2.0f * mu1 * mu2 + C1) * v1 /
                             ((mu1 * mu1 + mu2 * mu2 + C1) * v2);
                }
                if (lane1) {
                    float mu1 = A0[j].y, mu2 = A1[j].y;
                    float v1 = 2.0f * (A4[j].y - mu1 * mu2) + C2;
                    float v2 = (A2[j].y - mu1 * mu1) + (A3[j].y - mu2 * mu2) + C2;
                    sum_c += v1 / v2;
                    sum_s += (2.0f * mu1 * mu2 + C1) * v1 /
                             ((mu1 * mu1 + mu2 * mu2 + C1) * v2);
                }
            }
        }
    }
    sum_c = warp_sum(sum_c);
    sum_s = warp_sum(sum_s);
    __shared__ float shc[4], shs[4];
    int lane = threadIdx.x & 31, wid = threadIdx.x >> 5;
    if (lane == 0) { shc[wid] = sum_c; shs[wid] = sum_s; }
    __syncthreads();
    if (threadIdx.x == 0) {
        float tc = shc[0] + shc[1] + shc[2] + shc[3];
        float ts = shs[0] + shs[1] + shs[2] + shs[3];
        atomicAdd(&g_cs_sum[lvl],   (double)tc);
        atomicAdd(&g_ssim_sum[lvl], (double)ts);
    }
}

// ------------- avg pool 2x2x2, float4 in / float2 out -----------------------
template <int S>
__global__ void k_pool(const float* __restrict__ i1_0,
                       const float* __restrict__ i2_0, int lvl,
                       long poff_in, long poff_out) {
    constexpr int T  = S / 2;
    constexpr int TP = T / 2;
    constexpr int N  = 2 * T * T * TP;   // float2 outputs

    const float* i1 = (lvl == 0) ? i1_0 : (g_p1 + poff_in);
    const float* i2 = (lvl == 0) ? i2_0 : (g_p2 + poff_in);
    float* o1 = g_p1 + poff_out;
    float* o2 = g_p2 + poff_out;

    int idx = blockIdx.x * blockDim.x + threadIdx.x;
    if (idx >= N) return;
    int xp = idx % TP;
    int t  = idx / TP;
    int y  = t % T;
    int t2 = t / T;
    int z  = t2 % T;
    int b  = t2 / T;

    float2 r1 = make_float2(0.f, 0.f), r2 = make_float2(0.f, 0.f);
#pragma unroll
    for (int dz = 0; dz < 2; dz++)
#pragma unroll
        for (int dy = 0; dy < 2; dy++) {
            long base = (((long)b * S + 2 * z + dz) * S + 2 * y + dy) * S + 4 * xp;
            float4 v1 = *(const float4*)(i1 + base);
            float4 v2 = *(const float4*)(i2 + base);
            r1.x += v1.x + v1.y; r1.y += v1.z + v1.w;
            r2.x += v2.x + v2.y; r2.y += v2.z + v2.w;
        }
    r1.x *= 0.125f; r1.y *= 0.125f;
    r2.x *= 0.125f; r2.y *= 0.125f;
    long o = (((long)b * T + z) * T + y) * T + 2 * xp;
    *(float2*)(o1 + o) = r1;
    *(float2*)(o2 + o) = r2;
}

// ------------- final combine -------------------------------------------------
__global__ void k_final(float* out) {
    const double W[5]   = {0.0448, 0.2856, 0.3001, 0.2363, 0.1333};
    const double cnt[5] = {12057136.0, 1272112.0, 109744.0, 5488.0, 16.0};
    double p = 1.0;
    for (int l = 0; l < 4; l++) p *= pow(g_cs_sum[l] / cnt[l], W[l]);
    p *= pow(g_ssim_sum[4] / cnt[4], W[4]);
    out[0] = (float)p;
}

// ---------------------------------------------------------------------------
template <int S>
static void run_level(const float* i1, const float* i2, int lvl,
                      long poff_in, long poff_out) {
    constexpr int Wo  = S - 10;
    constexpr int WP  = (Wo + 3) & ~3;
    constexpr int WP4 = WP / 4;
    constexpr int RPB = (192 / WP4) < 1 ? 1 : (192 / WP4);
    int rows = 2 * S * S;
    k_pass1<S><<<(rows + RPB - 1) / RPB, WP4 * RPB>>>(i1, i2, lvl, poff_in);

    constexpr int TH = 12, NHT = (Wo + TH - 1) / TH, NQ = WP / 4;
    int tot2 = 10 * S * NHT * NQ;
    k_pass2<S><<<(tot2 + 127) / 128, 128>>>();

    constexpr int TD = 6, NDT = (Wo + TD - 1) / TD, NQ2 = WP / 2;
    int tot3 = 2 * NDT * Wo * NQ2;
    k_pass3<S><<<(tot3 + 127) / 128, 128>>>(lvl);

    if (lvl < 4) {
        constexpr int T = S / 2;
        int np = 2 * T * T * (T / 2);
        k_pool<S><<<(np + 127) / 128, 128>>>(i1, i2, lvl, poff_in, poff_out);
    }
}

extern "C" void kernel_launch(void* const* d_in, const int* in_sizes, int n_in,
                              void* d_out, int out_size) {
    const float* img1 = (const float*)d_in[0];
    const float* img2 = (const float*)d_in[1];

    k_init<<<1, 32>>>();
    run_level<192>(img1, img2, 0, 0,        h_off[1]);
    run_level<96>(img1, img2, 1, h_off[1], h_off[2]);
    run_level<48 >(img1, img2, 2, h_off[2], h_off[3]);
    run_level<24 >(img1, img2, 3, h_off[3], h_off[4]);
    run_level<12 >(img1, img2, 4, h_off[4], 0);
    k_final<<<1, 1>>>((float*)d_out);
}

// round 7
// speedup vs baseline: 3.6467x; 1.0660x over previous
#include <cuda_runtime.h>
#include <math.h>

#define WSZ 11

// Gaussian weights (sigma=1.5, ws=11) as compile-time constants -> FFMA-imm
__device__ constexpr float CWA[WSZ] = {
    0.00102838f, 0.00759875f, 0.03600080f, 0.10936069f, 0.21300554f,
    0.26601173f, 0.21300554f, 0.10936069f, 0.03600080f, 0.00759875f,
    0.00102838f};

// ---------------- static device state (no allocations allowed) --------------
__device__ double g_ssim_sum[5];
__device__ double g_cs_sum[5];
__device__ int    g_fmax[5];
__device__ int    g_fmin[5];

// pass1 out: [5 fields][2][S][S][WP]  (level0: 10*192*192*184)
__device__ float g_s1[67829760];
// pass2 out: [5 fields][2][S][Ho][WP] (level0: 10*192*182*184)
__device__ float g_s2[64289280];
// pooled pyramids (levels 1..4)
__device__ float g_p1[2021760];
__device__ float g_p2[2021760];

static const long h_off[5] = {0, 0, 1769472, 1990656, 2018304};

// ---------------------------------------------------------------------------
__global__ void k_init() {
    int t = threadIdx.x;
    if (t < 5) {
        g_ssim_sum[t] = 0.0;
        g_cs_sum[t]   = 0.0;
        g_fmax[t]     = 0;
        g_fmin[t]     = 0;
    }
}

// ------------- pass 1: W-conv + fused 2x2x2 avg-pool + flags ----------------
// block = 2x2 (d,h) row quad of one batch; emits conv rows + 1 pooled row
template <int S>
__global__ void k_pass1(const float* __restrict__ i1_0,
                        const float* __restrict__ i2_0, int lvl,
                        long poff_in, long poff_out) {
    constexpr int  Wo  = S - 10;
    constexpr int  WP  = (Wo + 3) & ~3;
    constexpr int  WP4 = WP / 4;
    constexpr int  SP  = S + 8;
    constexpr int  T   = S / 2;
    constexpr int  BT  = (4 * WP4 < 64) ? 64 : 4 * WP4;
    constexpr long FSZ = 2L * S * S * WP;

    __shared__ float s1[4 * SP];
    __shared__ float s2[4 * SP];
    __shared__ int   sfl;

    const float* i1 = (lvl == 0) ? i1_0 : (g_p1 + poff_in);
    const float* i2 = (lvl == 0) ? i2_0 : (g_p2 + poff_in);

    const int tid = threadIdx.x;
    int bid = blockIdx.x;
    int hp  = bid % (S / 2);
    int t0  = bid / (S / 2);
    int dp  = t0 % (S / 2);
    int b   = t0 / (S / 2);
    if (tid == 0) sfl = 0;

    bool mx = false, mn = false;
    for (int idx = tid; idx < 4 * SP; idx += BT) {
        int r  = idx / SP, ii = idx - r * SP;
        int d  = 2 * dp + (r >> 1);
        int h  = 2 * hp + (r & 1);
        float v1 = 0.f, v2 = 0.f;
        if (ii < S) {
            long gb = (((long)b * S + d) * S + h) * S + ii;
            v1 = i1[gb];
            v2 = i2[gb];
        }
        s1[idx] = v1;
        s2[idx] = v2;
        mx |= (v1 > 128.0f);
        mn |= (v1 < -0.5f);
    }
    __syncthreads();
    if (mx | mn) atomicOr(&sfl, (mx ? 1 : 0) | (mn ? 2 : 0));

    for (int task = tid; task < 4 * WP4; task += BT) {
        int r = task / WP4, q = task - r * WP4;
        int d = 2 * dp + (r >> 1);
        int h = 2 * hp + (r & 1);
        float xs[16], ys[16];
        {
            const float4* p1 = (const float4*)&s1[r * SP + 4 * q];
            const float4* p2 = (const float4*)&s2[r * SP + 4 * q];
#pragma unroll
            for (int m = 0; m < 4; m++) {
                float4 a = p1[m], bb = p2[m];
                xs[4 * m] = a.x;  xs[4 * m + 1] = a.y;  xs[4 * m + 2] = a.z;  xs[4 * m + 3] = a.w;
                ys[4 * m] = bb.x; ys[4 * m + 1] = bb.y; ys[4 * m + 2] = bb.z; ys[4 * m + 3] = bb.w;
            }
        }
        float xx[14], yy[14], xy[14];
#pragma unroll
        for (int m = 0; m < 14; m++) {
            xx[m] = xs[m] * xs[m];
            yy[m] = ys[m] * ys[m];
            xy[m] = xs[m] * ys[m];
        }
        float a1[4] = {0, 0, 0, 0}, a2[4] = {0, 0, 0, 0}, b1[4] = {0, 0, 0, 0},
              b2[4] = {0, 0, 0, 0}, b3[4] = {0, 0, 0, 0};
#pragma unroll
        for (int k = 0; k < WSZ; k++) {
            const float w = CWA[k];
#pragma unroll
            for (int j = 0; j < 4; j++) {
                a1[j] = fmaf(w, xs[k + j], a1[j]);
                a2[j] = fmaf(w, ys[k + j], a2[j]);
                b1[j] = fmaf(w, xx[k + j], b1[j]);
                b2[j] = fmaf(w, yy[k + j], b2[j]);
                b3[j] = fmaf(w, xy[k + j], b3[j]);
            }
        }
        long grow = ((long)b * S + d) * S + h;
        long o    = grow * WP + 4 * q;
        float4 v;
        v.x = a1[0]; v.y = a1[1]; v.z = a1[2]; v.w = a1[3];
        *(float4*)&g_s1[o] = v;
        v.x = a2[0]; v.y = a2[1]; v.z = a2[2]; v.w = a2[3];
        *(float4*)&g_s1[FSZ + o] = v;
        v.x = b1[0]; v.y = b1[1]; v.z = b1[2]; v.w = b1[3];
        *(float4*)&g_s1[2 * FSZ + o] = v;
        v.x = b2[0]; v.y = b2[1]; v.z = b2[2]; v.w = b2[3];
        *(float4*)&g_s1[3 * FSZ + o] = v;
        v.x = b3[0]; v.y = b3[1]; v.z = b3[2]; v.w = b3[3];
        *(float4*)&g_s1[4 * FSZ + o] = v;
    }

    if (lvl < 4) {
        float* o1 = g_p1 + poff_out;
        float* o2 = g_p2 + poff_out;
        long orow = (((long)b * T + dp) * T + hp) * T;
        for (int x = tid; x < T; x += BT) {
            float r1 = 0.f, r2 = 0.f;
#pragma unroll
            for (int r = 0; r < 4; r++) {
                r1 += s1[r * SP + 2 * x] + s1[r * SP + 2 * x + 1];
                r2 += s2[r * SP + 2 * x] + s2[r * SP + 2 * x + 1];
            }
            o1[orow + x] = r1 * 0.125f;
            o2[orow + x] = r2 * 0.125f;
        }
    }

    __syncthreads();
    if (tid == 0 && sfl) {
        if ((sfl & 1) && !g_fmax[lvl]) atomicOr(&g_fmax[lvl], 1);
        if ((sfl & 2) && !g_fmin[lvl]) atomicOr(&g_fmin[lvl], 1);
    }
}

// ------------- pass 2: H-conv, float4 x TH outputs per thread ---------------
template <int S>
__global__ void k_pass2() {
    constexpr int Wo = S - 10, Ho = S - 10;
    constexpr int WP  = (Wo + 3) & ~3;
    constexpr int NQ  = WP / 4;
    constexpr int TH  = 12;
    constexpr int NHT = (Ho + TH - 1) / TH;
    constexpr int TOT = 10 * S * NHT * NQ;

    int idx = blockIdx.x * blockDim.x + threadIdx.x;
    if (idx >= TOT) return;
    int quad = idx % NQ;
    int t    = idx / NQ;
    int ht   = t % NHT;
    int q    = t / NHT;
    int ho0  = ht * TH;

    const float* in = g_s1 + (long)q * S * WP + quad * 4;
    float4 acc[TH];
#pragma unroll
    for (int j = 0; j < TH; j++) acc[j] = make_float4(0.f, 0.f, 0.f, 0.f);

#pragma unroll
    for (int k = 0; k < TH + 10; k++) {
        int h = ho0 + k;
        if (h < S) {
            float4 v = *(const float4*)(in + h * WP);
#pragma unroll
            for (int j = 0; j < TH; j++) {
                int tt = k - j;
                if (tt >= 0 && tt < WSZ) {
                    const float w = CWA[tt];
                    acc[j].x = fmaf(w, v.x, acc[j].x);
                    acc[j].y = fmaf(w, v.y, acc[j].y);
                    acc[j].z = fmaf(w, v.z, acc[j].z);
                    acc[j].w = fmaf(w, v.w, acc[j].w);
                }
            }
        }
    }
    float* out = g_s2 + (long)q * Ho * WP + quad * 4;
#pragma unroll
    for (int j = 0; j < TH; j++) {
        int ho = ho0 + j;
        if (ho < Ho) *(float4*)(out + ho * WP) = acc[j];
    }
}

// ------------- pass 3: D-conv + SSIM/CS + reduction, float2 x TD ------------
__device__ __forceinline__ float warp_sum(float v) {
#pragma unroll
    for (int o = 16; o; o >>= 1) v += __shfl_down_sync(0xffffffffu, v, o);
    return v;
}

template <int S>
__global__ void k_pass3(int lvl) {
    constexpr int  Wo  = S - 10, Ho = Wo, Do = Wo;
    constexpr int  WP  = (Wo + 3) & ~3;
    constexpr int  NQ2 = WP / 2;
    constexpr int  TD  = 4;
    constexpr int  NDT = (Do + TD - 1) / TD;
    constexpr long HWP = (long)Ho * WP;
    constexpr long FST = 2L * S * HWP;
    constexpr int  TOT = 2 * NDT * Ho * NQ2;

    int idx = blockIdx.x * blockDim.x + threadIdx.x;
    float sum_s = 0.f, sum_c = 0.f;
    if (idx < TOT) {
        int p  = idx % NQ2;
        int t  = idx / NQ2;
        int ho = t % Ho;
        int t2 = t / Ho;
        int dt = t2 % NDT;
        int b  = t2 / NDT;
        int d0 = dt * TD;

        const float* base = g_s2 + (long)b * S * HWP + (long)ho * WP + 2 * p;
        float2 A0[TD], A1[TD], A2[TD], A3[TD], A4[TD];
#pragma unroll
        for (int j = 0; j < TD; j++) {
            A0[j] = A1[j] = A2[j] = A3[j] = A4[j] = make_float2(0.f, 0.f);
        }
#pragma unroll
        for (int k = 0; k < TD + 10; k++) {
            int d = d0 + k;
            if (d < S) {
                const float* pp = base + (long)d * HWP;
                float2 v0 = *(const float2*)(pp);
                float2 v1 = *(const float2*)(pp + FST);
                float2 v2 = *(const float2*)(pp + 2 * FST);
                float2 v3 = *(const float2*)(pp + 3 * FST);
                float2 v4 = *(const float2*)(pp + 4 * FST);
#pragma unroll
                for (int j = 0; j < TD; j++) {
                    int tt = k - j;
                    if (tt >= 0 && tt < WSZ) {
                        const float w = CWA[tt];
                        A0[j].x = fmaf(w, v0.x, A0[j].x); A0[j].y = fmaf(w, v0.y, A0[j].y);
                        A1[j].x = fmaf(w, v1.x, A1[j].x); A1[j].y = fmaf(w, v1.y, A1[j].y);
                        A2[j].x = fmaf(w, v2.x, A2[j].x); A2[j].y = fmaf(w, v2.y, A2[j].y);
                        A3[j].x = fmaf(w, v3.x, A3[j].x); A3[j].y = fmaf(w, v3.y, A3[j].y);
                        A4[j].x = fmaf(w, v4.x, A4[j].x); A4[j].y = fmaf(w, v4.y, A4[j].y);
                    }
                }
            }
        }
        float maxv = g_fmax[lvl] ? 255.0f : 1.0f;
        float minv = g_fmin[lvl] ? -1.0f : 0.0f;
        float L  = maxv - minv;
        float C1 = (0.01f * L) * (0.01f * L);
        float C2 = (0.03f * L) * (0.03f * L);
        bool lane0 = (2 * p) < Wo;
        bool lane1 = (2 * p + 1) < Wo;
#pragma unroll
        for (int j = 0; j < TD; j++) {
            if (d0 + j < Do) {
                if (lane0) {
                    float mu1 = A0[j].x, mu2 = A1[j].x;
                    float v1 = 2.0f * (A4[j].x - mu1 * mu2) + C2;
                    float v2 = (A2[j].x - mu1 * mu1) + (A3[j].x - mu2 * mu2) + C2;
                    sum_c += v1 / v2;
                    sum_s += (2.0f * mu1 * mu2 + C1) * v1 /
                             ((mu1 * mu1 + mu2 * mu2 + C1) * v2);
                }
                if (lane1) {
                    float mu1 = A0[j].y, mu2 = A1[j].y;
                    float v1 = 2.0f * (A4[j].y - mu1 * mu2) + C2;
                    float v2 = (A2[j].y - mu1 * mu1) + (A3[j].y - mu2 * mu2) + C2;
                    sum_c += v1 / v2;
                    sum_s += (2.0f * mu1 * mu2 + C1) * v1 /
                             ((mu1 * mu1 + mu2 * mu2 + C1) * v2);
                }
            }
        }
    }
    sum_c = warp_sum(sum_c);
    sum_s = warp_sum(sum_s);
    __shared__ float shc[4], shs[4];
    int lane = threadIdx.x & 31, wid = threadIdx.x >> 5;
    if (lane == 0) { shc[wid] = sum_c; shs[wid] = sum_s; }
    __syncthreads();
    if (threadIdx.x == 0) {
        float tc = shc[0] + shc[1] + shc[2] + shc[3];
        float ts = shs[0] + shs[1] + shs[2] + shs[3];
        atomicAdd(&g_cs_sum[lvl],   (double)tc);
        atomicAdd(&g_ssim_sum[lvl], (double)ts);
    }
}

// ------------- final combine -------------------------------------------------
__global__ void k_final(float* out) {
    const double W[5]   = {0.0448, 0.2856, 0.3001, 0.2363, 0.1333};
    const double cnt[5] = {12057136.0, 1272112.0, 109744.0, 5488.0, 16.0};
    double p = 1.0;
    for (int l = 0; l < 4; l++) p *= pow(g_cs_sum[l] / cnt[l], W[l]);
    p *= pow(g_ssim_sum[4] / cnt[4], W[4]);
    out[0] = (float)p;
}

// ---------------------------------------------------------------------------
template <int S>
static void run_level(const float* i1, const float* i2, int lvl,
                      long poff_in, long poff_out) {
    constexpr int Wo  = S - 10;
    constexpr int WP  = (Wo + 3) & ~3;
    constexpr int WP4 = WP / 4;
    constexpr int BT  = (4 * WP4 < 64) ? 64 : 4 * WP4;
    int nblk = 2 * (S / 2) * (S / 2);
    k_pass1<S><<<nblk, BT>>>(i1, i2, lvl, poff_in, poff_out);

    constexpr int TH = 12, NHT = (Wo + TH - 1) / TH, NQ = WP / 4;
    int tot2 = 10 * S * NHT * NQ;
    k_pass2<S><<<(tot2 + 127) / 128, 128>>>();

    constexpr int TD = 4, NDT = (Wo + TD - 1) / TD, NQ2 = WP / 2;
    int tot3 = 2 * NDT * Wo * NQ2;
    k_pass3<S><<<(tot3 + 127) / 128, 128>>>(lvl);
}

extern "C" void kernel_launch(void* const* d_in, const int* in_sizes, int n_in,
                              void* d_out, int out_size) {
    const float* img1 = (const float*)d_in[0];
    const float* img2 = (const float*)d_in[1];

    k_init<<<1, 32>>>();
    run_level<192>(img1, img2, 0, 0,        h_off[1]);
    run_level<96>(img1, img2, 1, h_off[1], h_off[2]);
    run_level<48 >(img1, img2, 2, h_off[2], h_off[3]);
    run_level<24 >(img1, img2, 3, h_off[3], h_off[4]);
    run_level<12 >(img1, img2, 4, h_off[4], 0);
    k_final<<<1, 1>>>((float*)d_out);
}

// round 8
// speedup vs baseline: 4.4210x; 1.2123x over previous
#include <cuda_runtime.h>
#include <cuda_fp16.h>
#include <math.h>

#define WSZ 11

// Gaussian weights (sigma=1.5, ws=11) as compile-time constants -> FFMA-imm
__device__ constexpr float CWA[WSZ] = {
    0.00102838f, 0.00759875f, 0.03600080f, 0.10936069f, 0.21300554f,
    0.26601173f, 0.21300554f, 0.10936069f, 0.03600080f, 0.00759875f,
    0.00102838f};

// ---------------- static device state (no allocations allowed) --------------
__device__ double g_ssim_sum[5];
__device__ double g_cs_sum[5];
__device__ int    g_fmax[5];
__device__ int    g_fmin[5];

// intermediates stored as fp16 (compute stays fp32)
__device__ __half g_s1[67829760];  // [5][2][S][S][WP]   level0
__device__ __half g_s2[64289280];  // [5][2][S][Ho][WP]  level0
// pooled pyramids (levels 1..4), fp32
__device__ float g_p1[2021760];
__device__ float g_p2[2021760];

static const long h_off[5] = {0, 0, 1769472, 1990656, 2018304};

// ---- half4 <-> float4 helpers ----------------------------------------------
__device__ __forceinline__ uint2 f4_to_h4(float4 v) {
    __half2 lo = __floats2half2_rn(v.x, v.y);
    __half2 hi = __floats2half2_rn(v.z, v.w);
    uint2 r;
    r.x = *(unsigned*)&lo;
    r.y = *(unsigned*)&hi;
    return r;
}
__device__ __forceinline__ float4 h4_to_f4(uint2 u) {
    __half2 lo = *(__half2*)&u.x;
    __half2 hi = *(__half2*)&u.y;
    float2 a = __half22float2(lo), b = __half22float2(hi);
    return make_float4(a.x, a.y, b.x, b.y);
}

// ---------------------------------------------------------------------------
__global__ void k_init() {
    int t = threadIdx.x;
    if (t < 5) {
        g_ssim_sum[t] = 0.0;
        g_cs_sum[t]   = 0.0;
        g_fmax[t]     = 0;
        g_fmin[t]     = 0;
    }
}

// ------------- pass 1: W-conv + fused 2x2x2 avg-pool + flags ----------------
template <int S>
__global__ void k_pass1(const float* __restrict__ i1_0,
                        const float* __restrict__ i2_0, int lvl,
                        long poff_in, long poff_out) {
    constexpr int  Wo  = S - 10;
    constexpr int  WP  = (Wo + 3) & ~3;
    constexpr int  WP4 = WP / 4;
    constexpr int  SP  = S + 8;
    constexpr int  T   = S / 2;
    constexpr int  BT  = (4 * WP4 < 64) ? 64 : 4 * WP4;
    constexpr long FSZ = 2L * S * S * WP;

    __shared__ float s1[4 * SP];
    __shared__ float s2[4 * SP];
    __shared__ int   sfl;

    const float* i1 = (lvl == 0) ? i1_0 : (g_p1 + poff_in);
    const float* i2 = (lvl == 0) ? i2_0 : (g_p2 + poff_in);

    const int tid = threadIdx.x;
    int bid = blockIdx.x;
    int hp  = bid % (S / 2);
    int t0  = bid / (S / 2);
    int dp  = t0 % (S / 2);
    int b   = t0 / (S / 2);
    if (tid == 0) sfl = 0;

    bool mx = false, mn = false;
    for (int idx = tid; idx < 4 * SP; idx += BT) {
        int r  = idx / SP, ii = idx - r * SP;
        int d  = 2 * dp + (r >> 1);
        int h  = 2 * hp + (r & 1);
        float v1 = 0.f, v2 = 0.f;
        if (ii < S) {
            long gb = (((long)b * S + d) * S + h) * S + ii;
            v1 = i1[gb];
            v2 = i2[gb];
        }
        s1[idx] = v1;
        s2[idx] = v2;
        mx |= (v1 > 128.0f);
        mn |= (v1 < -0.5f);
    }
    __syncthreads();
    if (mx | mn) atomicOr(&sfl, (mx ? 1 : 0) | (mn ? 2 : 0));

    for (int task = tid; task < 4 * WP4; task += BT) {
        int r = task / WP4, q = task - r * WP4;
        int d = 2 * dp + (r >> 1);
        int h = 2 * hp + (r & 1);
        float xs[16], ys[16];
        {
            const float4* p1 = (const float4*)&s1[r * SP + 4 * q];
            const float4* p2 = (const float4*)&s2[r * SP + 4 * q];
#pragma unroll
            for (int m = 0; m < 4; m++) {
                float4 a = p1[m], bb = p2[m];
                xs[4 * m] = a.x;  xs[4 * m + 1] = a.y;  xs[4 * m + 2] = a.z;  xs[4 * m + 3] = a.w;
                ys[4 * m] = bb.x; ys[4 * m + 1] = bb.y; ys[4 * m + 2] = bb.z; ys[4 * m + 3] = bb.w;
            }
        }
        float xx[14], yy[14], xy[14];
#pragma unroll
        for (int m = 0; m < 14; m++) {
            xx[m] = xs[m] * xs[m];
            yy[m] = ys[m] * ys[m];
            xy[m] = xs[m] * ys[m];
        }
        float a1[4] = {0, 0, 0, 0}, a2[4] = {0, 0, 0, 0}, b1[4] = {0, 0, 0, 0},
              b2[4] = {0, 0, 0, 0}, b3[4] = {0, 0, 0, 0};
#pragma unroll
        for (int k = 0; k < WSZ; k++) {
            const float w = CWA[k];
#pragma unroll
            for (int j = 0; j < 4; j++) {
                a1[j] = fmaf(w, xs[k + j], a1[j]);
                a2[j] = fmaf(w, ys[k + j], a2[j]);
                b1[j] = fmaf(w, xx[k + j], b1[j]);
                b2[j] = fmaf(w, yy[k + j], b2[j]);
                b3[j] = fmaf(w, xy[k + j], b3[j]);
            }
        }
        long grow = ((long)b * S + d) * S + h;
        long o    = grow * WP + 4 * q;
        *(uint2*)&g_s1[o]           = f4_to_h4(make_float4(a1[0], a1[1], a1[2], a1[3]));
        *(uint2*)&g_s1[FSZ + o]     = f4_to_h4(make_float4(a2[0], a2[1], a2[2], a2[3]));
        *(uint2*)&g_s1[2 * FSZ + o] = f4_to_h4(make_float4(b1[0], b1[1], b1[2], b1[3]));
        *(uint2*)&g_s1[3 * FSZ + o] = f4_to_h4(make_float4(b2[0], b2[1], b2[2], b2[3]));
        *(uint2*)&g_s1[4 * FSZ + o] = f4_to_h4(make_float4(b3[0], b3[1], b3[2], b3[3]));
    }

    if (lvl < 4) {
        float* o1 = g_p1 + poff_out;
        float* o2 = g_p2 + poff_out;
        long orow = (((long)b * T + dp) * T + hp) * T;
        for (int x = tid; x < T; x += BT) {
            float r1 = 0.f, r2 = 0.f;
#pragma unroll
            for (int r = 0; r < 4; r++) {
                r1 += s1[r * SP + 2 * x] + s1[r * SP + 2 * x + 1];
                r2 += s2[r * SP + 2 * x] + s2[r * SP + 2 * x + 1];
            }
            o1[orow + x] = r1 * 0.125f;
            o2[orow + x] = r2 * 0.125f;
        }
    }

    __syncthreads();
    if (tid == 0 && sfl) {
        if ((sfl & 1) && !g_fmax[lvl]) atomicOr(&g_fmax[lvl], 1);
        if ((sfl & 2) && !g_fmin[lvl]) atomicOr(&g_fmin[lvl], 1);
    }
}

// ------------- pass 2: H-conv, half4 x TH outputs per thread ----------------
template <int S>
__global__ void k_pass2() {
    constexpr int Wo = S - 10, Ho = S - 10;
    constexpr int WP  = (Wo + 3) & ~3;
    constexpr int NQ  = WP / 4;
    constexpr int TH  = 12;
    constexpr int NHT = (Ho + TH - 1) / TH;
    constexpr int TOT = 10 * S * NHT * NQ;

    int idx = blockIdx.x * blockDim.x + threadIdx.x;
    if (idx >= TOT) return;
    int quad = idx % NQ;
    int t    = idx / NQ;
    int ht   = t % NHT;
    int q    = t / NHT;
    int ho0  = ht * TH;

    const __half* in = g_s1 + (long)q * S * WP + quad * 4;
    float4 acc[TH];
#pragma unroll
    for (int j = 0; j < TH; j++) acc[j] = make_float4(0.f, 0.f, 0.f, 0.f);

#pragma unroll
    for (int k = 0; k < TH + 10; k++) {
        int h = ho0 + k;
        if (h < S) {
            float4 v = h4_to_f4(*(const uint2*)(in + (long)h * WP));
#pragma unroll
            for (int j = 0; j < TH; j++) {
                int tt = k - j;
                if (tt >= 0 && tt < WSZ) {
                    const float w = CWA[tt];
                    acc[j].x = fmaf(w, v.x, acc[j].x);
                    acc[j].y = fmaf(w, v.y, acc[j].y);
                    acc[j].z = fmaf(w, v.z, acc[j].z);
                    acc[j].w = fmaf(w, v.w, acc[j].w);
                }
            }
        }
    }
    __half* out = g_s2 + (long)q * Ho * WP + quad * 4;
#pragma unroll
    for (int j = 0; j < TH; j++) {
        int ho = ho0 + j;
        if (ho < Ho) *(uint2*)(out + (long)ho * WP) = f4_to_h4(acc[j]);
    }
}

// ------------- pass 3: D-conv + SSIM/CS + reduction, half2 x TD -------------
__device__ __forceinline__ float warp_sum(float v) {
#pragma unroll
    for (int o = 16; o; o >>= 1) v += __shfl_down_sync(0xffffffffu, v, o);
    return v;
}

template <int S>
__global__ void k_pass3(int lvl) {
    constexpr int  Wo  = S - 10, Ho = Wo, Do = Wo;
    constexpr int  WP  = (Wo + 3) & ~3;
    constexpr int  NQ2 = WP / 2;
    constexpr int  TD  = 6;
    constexpr int  NDT = (Do + TD - 1) / TD;
    constexpr long HWP = (long)Ho * WP;
    constexpr long FST = 2L * S * HWP;
    constexpr int  TOT = 2 * NDT * Ho * NQ2;

    int idx = blockIdx.x * blockDim.x + threadIdx.x;
    float sum_s = 0.f, sum_c = 0.f;
    if (idx < TOT) {
        int p  = idx % NQ2;
        int t  = idx / NQ2;
        int ho = t % Ho;
        int t2 = t / Ho;
        int dt = t2 % NDT;
        int b  = t2 / NDT;
        int d0 = dt * TD;

        const __half* base = g_s2 + (long)b * S * HWP + (long)ho * WP + 2 * p;
        float2 A0[TD], A1[TD], A2[TD], A3[TD], A4[TD];
#pragma unroll
        for (int j = 0; j < TD; j++) {
            A0[j] = A1[j] = A2[j] = A3[j] = A4[j] = make_float2(0.f, 0.f);
        }
#pragma unroll
        for (int k = 0; k < TD + 10; k++) {
            int d = d0 + k;
            if (d < S) {
                const __half* pp = base + (long)d * HWP;
                float2 v0 = __half22float2(*(const __half2*)(pp));
                float2 v1 = __half22float2(*(const __half2*)(pp + FST));
                float2 v2 = __half22float2(*(const __half2*)(pp + 2 * FST));
                float2 v3 = __half22float2(*(const __half2*)(pp + 3 * FST));
                float2 v4 = __half22float2(*(const __half2*)(pp + 4 * FST));
#pragma unroll
                for (int j = 0; j < TD; j++) {
                    int tt = k - j;
                    if (tt >= 0 && tt < WSZ) {
                        const float w = CWA[tt];
                        A0[j].x = fmaf(w, v0.x, A0[j].x); A0[j].y = fmaf(w, v0.y, A0[j].y);
                        A1[j].x = fmaf(w, v1.x, A1[j].x); A1[j].y = fmaf(w, v1.y, A1[j].y);
                        A2[j].x = fmaf(w, v2.x, A2[j].x); A2[j].y = fmaf(w, v2.y, A2[j].y);
                        A3[j].x = fmaf(w, v3.x, A3[j].x); A3[j].y = fmaf(w, v3.y, A3[j].y);
                        A4[j].x = fmaf(w, v4.x, A4[j].x); A4[j].y = fmaf(w, v4.y, A4[j].y);
                    }
                }
            }
        }
        float maxv = g_fmax[lvl] ? 255.0f : 1.0f;
        float minv = g_fmin[lvl] ? -1.0f : 0.0f;
        float L  = maxv - minv;
        float C1 = (0.01f * L) * (0.01f * L);
        float C2 = (0.03f * L) * (0.03f * L);
        bool lane0 = (2 * p) < Wo;
        bool lane1 = (2 * p + 1) < Wo;
#pragma unroll
        for (int j = 0; j < TD; j++) {
            if (d0 + j < Do) {
                if (lane0) {
                    float mu1 = A0[j].x, mu2 = A1[j].x;
                    float v1 = 2.0f * (A4[j].x - mu1 * mu2) + C2;
                    float v2 = (A2[j].x - mu1 * mu1) + (A3[j].x - mu2 * mu2) + C2;
                    sum_c += v1 / v2;
                    sum_s += (2.0f * mu1 * mu2 + C1) * v1 /
                             ((mu1 * mu1 + mu2 * mu2 + C1) * v2);
                }
                if (lane1) {
                    float mu1 = A0[j].y, mu2 = A1[j].y;
                    float v1 = 2.0f * (A4[j].y - mu1 * mu2) + C2;
                    float v2 = (A2[j].y - mu1 * mu1) + (A3[j].y - mu2 * mu2) + C2;
                    sum_c += v1 / v2;
                    sum_s += (2.0f * mu1 * mu2 + C1) * v1 /
                             ((mu1 * mu1 + mu2 * mu2 + C1) * v2);
                }
            }
        }
    }
    sum_c = warp_sum(sum_c);
    sum_s = warp_sum(sum_s);
    __shared__ float shc[4], shs[4];
    int lane = threadIdx.x & 31, wid = threadIdx.x >> 5;
    if (lane == 0) { shc[wid] = sum_c; shs[wid] = sum_s; }
    __syncthreads();
    if (threadIdx.x == 0) {
        float tc = shc[0] + shc[1] + shc[2] + shc[3];
        float ts = shs[0] + shs[1] + shs[2] + shs[3];
        atomicAdd(&g_cs_sum[lvl],   (double)tc);
        atomicAdd(&g_ssim_sum[lvl], (double)ts);
    }
}

// ------------- final combine -------------------------------------------------
__global__ void k_final(float* out) {
    const double W[5]   = {0.0448, 0.2856, 0.3001, 0.2363, 0.1333};
    const double cnt[5] = {12057136.0, 1272112.0, 109744.0, 5488.0, 16.0};
    double p = 1.0;
    for (int l = 0; l < 4; l++) p *= pow(g_cs_sum[l] / cnt[l], W[l]);
    p *= pow(g_ssim_sum[4] / cnt[4], W[4]);
    out[0] = (float)p;
}

// ---------------------------------------------------------------------------
template <int S>
static void run_level(const float* i1, const float* i2, int lvl,
                      long poff_in, long poff_out) {
    constexpr int Wo  = S - 10;
    constexpr int WP  = (Wo + 3) & ~3;
    constexpr int WP4 = WP / 4;
    constexpr int BT  = (4 * WP4 < 64) ? 64 : 4 * WP4;
    int nblk = 2 * (S / 2) * (S / 2);
    k_pass1<S><<<nblk, BT>>>(i1, i2, lvl, poff_in, poff_out);

    constexpr int TH = 12, NHT = (Wo + TH - 1) / TH, NQ = WP / 4;
    int tot2 = 10 * S * NHT * NQ;
    k_pass2<S><<<(tot2 + 127) / 128, 128>>>();

    constexpr int TD = 6, NDT = (Wo + TD - 1) / TD, NQ2 = WP / 2;
    int tot3 = 2 * NDT * Wo * NQ2;
    k_pass3<S><<<(tot3 + 127) / 128, 128>>>(lvl);
}

extern "C" void kernel_launch(void* const* d_in, const int* in_sizes, int n_in,
                              void* d_out, int out_size) {
    const float* img1 = (const float*)d_in[0];
    const float* img2 = (const float*)d_in[1];

    k_init<<<1, 32>>>();
    run_level<192>(img1, img2, 0, 0,        h_off[1]);
    run_level<96>(img1, img2, 1, h_off[1], h_off[2]);
    run_level<48 >(img1, img2, 2, h_off[2], h_off[3]);
    run_level<24 >(img1, img2, 3, h_off[3], h_off[4]);
    run_level<12 >(img1, img2, 4, h_off[4], 0);
    k_final<<<1, 1>>>((float*)d_out);
}